// round 2
// baseline (speedup 1.0000x reference)
#include <cuda_runtime.h>
#include <math.h>

#define N_EDGES_HINT 100000
#define FEATD   72
#define RTOT    1216
#define RSHD    25
#define BE      16
#define NT      256
#define XPAD    104
#define SWISH_SCALE 1.679177f

// ---------------------------------------------------------------------------
// Precomputed-constant storage: real Wigner-3j coupling tensors, flattened.
// 19 (lo,li,lf) combos, total 1225 floats. Recomputed per launch (cheap,
// deterministic, graph-capturable).
// ---------------------------------------------------------------------------
__device__ float g_C3[1225];

__constant__ int CMB_LO[19] = {0,0,0,1,1,1,1,1,1,1,2,2,2,2,2,2,2,2,2};
__constant__ int CMB_LI[19] = {0,1,2,0,1,1,1,2,2,2,0,1,1,1,2,2,2,2,2};
__constant__ int CMB_LF[19] = {0,1,2,1,0,1,2,1,2,3,2,1,2,3,0,1,2,3,4};
__constant__ int CMB_OFF[20] = {0,1,10,35,44,53,80,125,170,245,350,375,420,495,600,625,700,825,1000,1225};

// pair p = i*3 + j   (i: output irrep, j: input irrep), l = {0,1,2}, mul = 8
__constant__ int P_LO[9]   = {0,0,0,1,1,1,2,2,2};
__constant__ int P_LI[9]   = {0,1,2,0,1,2,0,1,2};
__constant__ int P_NLF[9]  = {1,1,1,1,3,3,1,3,5};
__constant__ int P_ROFF[9] = {0,64,128,192,256,448,640,704,896};
__constant__ int P_LFMIN[9]= {0,1,2,1,0,1,2,1,0};
__constant__ int P_FOFF[3] = {0,8,32};
__constant__ int P_C3OFF[9][5] = {
    {0,0,0,0,0},{1,0,0,0,0},{10,0,0,0,0},{35,0,0,0,0},
    {44,53,80,0,0},{125,170,245,0,0},{350,0,0,0,0},
    {375,420,495,0,0},{600,625,700,825,1000}};

// ---------------------------------------------------------------------------
// Wigner 3j (complex basis, Racah) + real change-of-basis, in double
// ---------------------------------------------------------------------------
__device__ __forceinline__ double d_fact(int n) {
    double f = 1.0;
    for (int i = 2; i <= n; ++i) f *= (double)i;
    return f;
}

__device__ double w3j_d(int j1, int j2, int j3, int m1, int m2, int m3) {
    if (m1 + m2 + m3 != 0) return 0.0;
    if (j3 < abs(j1 - j2) || j3 > j1 + j2) return 0.0;
    int t1 = j2 - m1 - j3, t2 = j1 + m2 - j3;
    int kmin = max(0, max(t1, t2));
    int kmax = min(j1 + j2 - j3, min(j1 - m1, j2 + m2));
    double s = 0.0;
    for (int k = kmin; k <= kmax; ++k) {
        double term = 1.0 / (d_fact(k) * d_fact(k - t1) * d_fact(k - t2) *
                             d_fact(j1 + j2 - j3 - k) * d_fact(j1 - m1 - k) * d_fact(j2 + m2 - k));
        s += ((k & 1) ? -term : term);
    }
    double pref = sqrt(
        d_fact(j1 + j2 - j3) * d_fact(j1 - j2 + j3) * d_fact(-j1 + j2 + j3) / d_fact(j1 + j2 + j3 + 1)
        * d_fact(j1 + m1) * d_fact(j1 - m1) * d_fact(j2 + m2) * d_fact(j2 - m2)
        * d_fact(j3 + m3) * d_fact(j3 - m3));
    if ((j1 - j2 - m3) & 1) pref = -pref;
    return pref * s;
}

// Row a of the complex->real COB matrix U(l): at most 2 nonzeros.
__device__ __forceinline__ int cob_row(int l, int a, int* cols, double* re, double* im) {
    const double s = 0.70710678118654752440;
    if (a == l) { cols[0] = l; re[0] = 1.0; im[0] = 0.0; return 1; }
    if (a > l) {
        int m = a - l; double sg = (m & 1) ? -1.0 : 1.0;
        cols[0] = l + m; re[0] = sg * s; im[0] = 0.0;
        cols[1] = l - m; re[1] = s;      im[1] = 0.0;
        return 2;
    }
    int m = l - a; double sg = (m & 1) ? -1.0 : 1.0;
    cols[0] = l - m; re[0] = 0.0; im[0] = s;
    cols[1] = l + m; re[1] = 0.0; im[1] = -sg * s;
    return 2;
}

// ---------------------------------------------------------------------------
// init kernel: zero the output AND (block 0) build the C3 tensors
// ---------------------------------------------------------------------------
__global__ void init_kernel(float* __restrict__ out, int out_size) {
    for (long i = (long)blockIdx.x * blockDim.x + threadIdx.x; i < out_size;
         i += (long)gridDim.x * blockDim.x)
        out[i] = 0.0f;

    if (blockIdx.x != 0) return;

    __shared__ double s_re[1225];
    __shared__ double s_im[1225];
    int tid = threadIdx.x;

    for (int idx = tid; idx < 1225; idx += blockDim.x) {
        int t = 0;
        while (!(idx < CMB_OFF[t + 1])) ++t;
        int lo = CMB_LO[t], li = CMB_LI[t], lf = CMB_LF[t];
        int d2 = 2 * li + 1, d3 = 2 * lf + 1;
        int rel = idx - CMB_OFF[t];
        int a = rel / (d2 * d3), b = (rel / d3) % d2, c = rel % d3;

        int c1[2], c2[2], c3c[2];
        double r1[2], i1[2], r2[2], i2[2], r3[2], i3[2];
        int n1 = cob_row(lo, a, c1, r1, i1);
        int n2 = cob_row(li, b, c2, r2, i2);
        int n3 = cob_row(lf, c, c3c, r3, i3);

        double tr = 0.0, ti = 0.0;
        for (int x = 0; x < n1; ++x)
            for (int y = 0; y < n2; ++y)
                for (int z = 0; z < n3; ++z) {
                    int m1 = c1[x] - lo, m2 = c2[y] - li, m3 = c3c[z] - lf;
                    if (m1 + m2 + m3 != 0) continue;
                    double w = w3j_d(lo, li, lf, m1, m2, m3);
                    if (w == 0.0) continue;
                    double ar = r1[x] * r2[y] - i1[x] * i2[y];
                    double ai = r1[x] * i2[y] + i1[x] * r2[y];
                    double br = ar * r3[z] - ai * i3[z];
                    double bi = ar * i3[z] + ai * r3[z];
                    tr += br * w; ti += bi * w;
                }
        s_re[idx] = tr; s_im[idx] = ti;
    }
    __syncthreads();

    if (tid < 19) {
        int off = CMB_OFF[tid], end = CMB_OFF[tid + 1];
        double nr = 0.0, ni = 0.0;
        for (int k = off; k < end; ++k) { nr += s_re[k] * s_re[k]; ni += s_im[k] * s_im[k]; }
        bool useRe = (nr >= ni);
        double nn = sqrt(useRe ? nr : ni);
        double inv = (nn > 0.0) ? 1.0 / nn : 0.0;
        for (int k = off; k < end; ++k)
            g_C3[k] = (float)((useRe ? s_re[k] : s_im[k]) * inv);
    }
}

// ---------------------------------------------------------------------------
// main fused kernel: per 16-edge tile — radial MLP -> streamed W3 GEMM ->
// tensor-product message -> scatter-add
// ---------------------------------------------------------------------------
__device__ __forceinline__ float swish_act(float a) {
    return SWISH_SCALE * a / (1.0f + __expf(-a));
}

extern "C" __global__ void __launch_bounds__(NT)
edge_kernel(const float* __restrict__ feat, const int* __restrict__ eidx,
            const float* __restrict__ radii, const float* __restrict__ rsh,
            const float* __restrict__ W0, const float* __restrict__ W1,
            const float* __restrict__ W2, const float* __restrict__ W3,
            float* __restrict__ out, int E)
{
    extern __shared__ float sm[];
    float* s_h0  = sm;                    // [BE][XPAD]
    float* s_h1  = s_h0  + BE * XPAD;     // [BE][XPAD]  (holds x3 after MLP)
    float* s_R   = s_h1  + BE * XPAD;     // [BE][320]
    float* s_T   = s_R   + BE * 320;      // [BE][200]
    float* s_F   = s_T   + BE * 200;      // [BE][72]
    float* s_acc = s_F   + BE * 72;       // [BE][72]
    float* s_rsh = s_acc + BE * 72;       // [BE][25]
    int*   s_tgt = (int*)(s_rsh + BE * 25); // [BE]

    const int tid = threadIdx.x;
    const int e0  = blockIdx.x * BE;

    // ---- load per-edge data ----
    for (int t = tid; t < BE; t += NT) {
        int e = e0 + t;
        s_tgt[t] = (e < E) ? eidx[E + e] : -1;
    }
    for (int t = tid; t < BE * FEATD; t += NT) {
        int le = t / FEATD, k = t % FEATD;
        int e = e0 + le;
        float v = 0.0f;
        if (e < E) v = feat[(long)eidx[e] * FEATD + k];
        s_F[le * FEATD + k] = v;
        s_acc[le * FEATD + k] = 0.0f;
    }
    for (int t = tid; t < BE * RSHD; t += NT) {
        int le = t / RSHD, k = t % RSHD;
        int e = e0 + le;
        s_rsh[le * RSHD + k] = (e < E) ? rsh[e * RSHD + k] : 0.0f;
    }
    // gaussian radial basis
    for (int t = tid; t < BE * 10; t += NT) {
        int le = t / 10, k = t % 10;
        int e = e0 + le;
        float r = (e < E) ? radii[e] : 0.0f;
        const float sigma = 2.5f / 9.0f;
        float c = 0.7f + (float)k * sigma;
        float d = (r - c) / sigma;
        s_h0[le * XPAD + k] = __expf(-d * d);
    }
    __syncthreads();

    // ---- layer 0: [10] -> [100], scale 1/sqrt(10), swish ----
    for (int t = tid; t < BE * 25; t += NT) {
        int le = t / 25, o4 = (t % 25) * 4;
        float a0 = 0, a1 = 0, a2 = 0, a3 = 0;
        const float* xr = s_h0 + le * XPAD;
        #pragma unroll
        for (int h = 0; h < 10; ++h) {
            float x = xr[h];
            float4 w = *(const float4*)(W0 + h * 100 + o4);
            a0 += x * w.x; a1 += x * w.y; a2 += x * w.z; a3 += x * w.w;
        }
        const float sc = 0.31622776601683794f;
        float* o = s_h1 + le * XPAD + o4;
        o[0] = swish_act(a0 * sc); o[1] = swish_act(a1 * sc);
        o[2] = swish_act(a2 * sc); o[3] = swish_act(a3 * sc);
    }
    __syncthreads();

    // ---- layer 1: [100] -> [100], scale 0.1, swish ----
    for (int t = tid; t < BE * 25; t += NT) {
        int le = t / 25, o4 = (t % 25) * 4;
        float a0 = 0, a1 = 0, a2 = 0, a3 = 0;
        const float* xr = s_h1 + le * XPAD;
        #pragma unroll 4
        for (int h = 0; h < 100; ++h) {
            float x = xr[h];
            float4 w = *(const float4*)(W1 + h * 100 + o4);
            a0 += x * w.x; a1 += x * w.y; a2 += x * w.z; a3 += x * w.w;
        }
        float* o = s_h0 + le * XPAD + o4;
        o[0] = swish_act(a0 * 0.1f); o[1] = swish_act(a1 * 0.1f);
        o[2] = swish_act(a2 * 0.1f); o[3] = swish_act(a3 * 0.1f);
    }
    __syncthreads();

    // ---- layer 2: [100] -> [100], scale 0.1, swish -> x3 in s_h1 ----
    for (int t = tid; t < BE * 25; t += NT) {
        int le = t / 25, o4 = (t % 25) * 4;
        float a0 = 0, a1 = 0, a2 = 0, a3 = 0;
        const float* xr = s_h0 + le * XPAD;
        #pragma unroll 4
        for (int h = 0; h < 100; ++h) {
            float x = xr[h];
            float4 w = *(const float4*)(W2 + h * 100 + o4);
            a0 += x * w.x; a1 += x * w.y; a2 += x * w.z; a3 += x * w.w;
        }
        float* o = s_h1 + le * XPAD + o4;
        o[0] = swish_act(a0 * 0.1f); o[1] = swish_act(a1 * 0.1f);
        o[2] = swish_act(a2 * 0.1f); o[3] = swish_act(a3 * 0.1f);
    }
    __syncthreads();

    const float NRM[3] = {sqrtf(12.566370614359172f / 24.0f),
                          sqrtf(12.566370614359172f * 3.0f / 56.0f),
                          sqrtf(12.566370614359172f * 5.0f / 72.0f)};

    // ---- 9 irrep-pair blocks: streamed W3 GEMM + tensor contraction ----
    for (int p = 0; p < 9; ++p) {
        const int lo = P_LO[p], li = P_LI[p], nlf = P_NLF[p];
        const int no = 2 * lo + 1, ni = 2 * li + 1;
        const int chunk = 64 * nlf;
        const int nq = chunk >> 2;
        const float* W3c = W3 + P_ROFF[p];

        // phase 1: R chunk = x3 @ W3[:, roff:roff+chunk] * 0.1
        for (int t = tid; t < BE * nq; t += NT) {
            int le = t / nq, c4 = (t % nq) * 4;
            const float* Wp = W3c + c4;
            const float* xr = s_h1 + le * XPAD;
            float a0 = 0, a1 = 0, a2 = 0, a3 = 0;
            #pragma unroll 4
            for (int h = 0; h < 100; ++h) {
                float x = xr[h];
                float4 w = *(const float4*)(Wp + (long)h * RTOT);
                a0 += x * w.x; a1 += x * w.y; a2 += x * w.z; a3 += x * w.w;
            }
            float* Rr = s_R + le * 320 + c4;
            Rr[0] = a0 * 0.1f; Rr[1] = a1 * 0.1f;
            Rr[2] = a2 * 0.1f; Rr[3] = a3 * 0.1f;
        }

        // phase 1b: T[o][v][fi] = sum_mi (sum_mf C3[o,mi,mf] * rsh[lf^2+mf]) * F[v,mi]
        const int tsz = no * 8 * nlf;
        const int j = p % 3;
        for (int t = tid; t < BE * tsz; t += NT) {
            int le = t / tsz, x = t % tsz;
            int o = x / (8 * nlf);
            int rem = x % (8 * nlf);
            int v = rem / nlf, fi = rem % nlf;
            int lf = P_LFMIN[p] + fi;
            int nf = 2 * lf + 1;
            const float* C  = g_C3 + P_C3OFF[p][fi] + o * ni * nf;
            const float* rr = s_rsh + le * RSHD + lf * lf;
            const float* Fv = s_F + le * FEATD + P_FOFF[j] + v * ni;
            float a = 0.0f;
            for (int mi = 0; mi < ni; ++mi) {
                float kv = 0.0f;
                for (int mf = 0; mf < nf; ++mf) kv += C[mi * nf + mf] * rr[mf];
                a += kv * Fv[mi];
            }
            s_T[le * 200 + x] = a;
        }
        __syncthreads();

        // phase 2: acc[u][o] += NRM * sum_{v,fi} R[u,v,fi] * T[o,v,fi]
        const float nrm = NRM[p / 3];
        const int osz = 8 * no;
        const int aoff = P_FOFF[p / 3];
        const int kl = 8 * nlf;
        for (int t = tid; t < BE * osz; t += NT) {
            int le = t / osz, y = t % osz;
            int u = y / no, o = y % no;
            const float* Rr = s_R + le * 320 + u * kl;
            const float* Tr = s_T + le * 200 + o * kl;
            float a = 0.0f;
            for (int k = 0; k < kl; ++k) a += Rr[k] * Tr[k];
            s_acc[le * FEATD + aoff + y] += nrm * a;
        }
        __syncthreads();
    }

    // ---- scatter-add to target nodes ----
    for (int t = tid; t < BE * FEATD; t += NT) {
        int le = t / FEATD, k = t % FEATD;
        int tg = s_tgt[le];
        if (tg >= 0) atomicAdd(out + (long)tg * FEATD + k, s_acc[le * FEATD + k]);
    }
}

// ---------------------------------------------------------------------------
extern "C" void kernel_launch(void* const* d_in, const int* in_sizes, int n_in,
                              void* d_out, int out_size)
{
    const float* feat  = (const float*)d_in[0];
    const int*   eidx  = (const int*)  d_in[1];
    const float* radii = (const float*)d_in[2];
    const float* rshp  = (const float*)d_in[3];
    const float* W0    = (const float*)d_in[4];
    const float* W1    = (const float*)d_in[5];
    const float* W2    = (const float*)d_in[6];
    const float* W3    = (const float*)d_in[7];
    float* out = (float*)d_out;

    int E = in_sizes[2];   // radii element count = number of edges

    init_kernel<<<256, 256>>>(out, out_size);

    size_t smem = (size_t)(2 * BE * XPAD + BE * 320 + BE * 200 + 2 * BE * 72 + BE * 25) * sizeof(float)
                + (size_t)BE * sizeof(int);
    cudaFuncSetAttribute(edge_kernel, cudaFuncAttributeMaxDynamicSharedMemorySize, (int)smem);

    int nb = (E + BE - 1) / BE;
    edge_kernel<<<nb, NT, smem>>>(feat, eidx, radii, rshp, W0, W1, W2, W3, out, E);
}

// round 5
// speedup vs baseline: 1.0183x; 1.0183x over previous
#include <cuda_runtime.h>
#include <math.h>

#define FEATD   72
#define RTOT    1216
#define RSHD    25
#define BE      16
#define NT      256
#define RHALF   640      // cols in half 1 (pairs 0..5); half 2 = 576 (pairs 6..8)
#define TTOT    552
#define SWISH_SCALE 1.679177f

// ---------------------------------------------------------------------------
// Precomputed-constant storage: real Wigner-3j coupling tensors, flattened.
// ---------------------------------------------------------------------------
__device__ float g_C3[1225];

__constant__ int CMB_LO[19] = {0,0,0,1,1,1,1,1,1,1,2,2,2,2,2,2,2,2,2};
__constant__ int CMB_LI[19] = {0,1,2,0,1,1,1,2,2,2,0,1,1,1,2,2,2,2,2};
__constant__ int CMB_LF[19] = {0,1,2,1,0,1,2,1,2,3,2,1,2,3,0,1,2,3,4};
__constant__ int CMB_OFF[20] = {0,1,10,35,44,53,80,125,170,245,350,375,420,495,600,625,700,825,1000,1225};

// pair p = i*3 + j (i: output irrep, j: input irrep), l = {0,1,2}, mul = 8
__constant__ int P_LO[9]   = {0,0,0,1,1,1,2,2,2};
__constant__ int P_LI[9]   = {0,1,2,0,1,2,0,1,2};
__constant__ int P_NLF[9]  = {1,1,1,1,3,3,1,3,5};
__constant__ int P_ROFF[9] = {0,64,128,192,256,448,640,704,896};
__constant__ int P_LFMIN[9]= {0,1,2,1,0,1,2,1,0};
__constant__ int P_FOFF[3] = {0,8,32};
__constant__ int T_OFF[9]  = {0,8,16,24,48,120,192,232,352};
__constant__ int P_C3OFF[9][5] = {
    {0,0,0,0,0},{1,0,0,0,0},{10,0,0,0,0},{35,0,0,0,0},
    {44,53,80,0,0},{125,170,245,0,0},{350,0,0,0,0},
    {375,420,495,0,0},{600,625,700,825,1000}};

// ---------------------------------------------------------------------------
// Wigner 3j (complex basis, Racah) + real change-of-basis, in double
// ---------------------------------------------------------------------------
__device__ __forceinline__ double d_fact(int n) {
    double f = 1.0;
    for (int i = 2; i <= n; ++i) f *= (double)i;
    return f;
}

__device__ double w3j_d(int j1, int j2, int j3, int m1, int m2, int m3) {
    if (m1 + m2 + m3 != 0) return 0.0;
    if (j3 < abs(j1 - j2) || j3 > j1 + j2) return 0.0;
    int t1 = j2 - m1 - j3, t2 = j1 + m2 - j3;
    int kmin = max(0, max(t1, t2));
    int kmax = min(j1 + j2 - j3, min(j1 - m1, j2 + m2));
    double s = 0.0;
    for (int k = kmin; k <= kmax; ++k) {
        double term = 1.0 / (d_fact(k) * d_fact(k - t1) * d_fact(k - t2) *
                             d_fact(j1 + j2 - j3 - k) * d_fact(j1 - m1 - k) * d_fact(j2 + m2 - k));
        s += ((k & 1) ? -term : term);
    }
    double pref = sqrt(
        d_fact(j1 + j2 - j3) * d_fact(j1 - j2 + j3) * d_fact(-j1 + j2 + j3) / d_fact(j1 + j2 + j3 + 1)
        * d_fact(j1 + m1) * d_fact(j1 - m1) * d_fact(j2 + m2) * d_fact(j2 - m2)
        * d_fact(j3 + m3) * d_fact(j3 - m3));
    if ((j1 - j2 - m3) & 1) pref = -pref;
    return pref * s;
}

__device__ __forceinline__ int cob_row(int l, int a, int* cols, double* re, double* im) {
    const double s = 0.70710678118654752440;
    if (a == l) { cols[0] = l; re[0] = 1.0; im[0] = 0.0; return 1; }
    if (a > l) {
        int m = a - l; double sg = (m & 1) ? -1.0 : 1.0;
        cols[0] = l + m; re[0] = sg * s; im[0] = 0.0;
        cols[1] = l - m; re[1] = s;      im[1] = 0.0;
        return 2;
    }
    int m = l - a; double sg = (m & 1) ? -1.0 : 1.0;
    cols[0] = l - m; re[0] = 0.0; im[0] = s;
    cols[1] = l + m; re[1] = 0.0; im[1] = -sg * s;
    return 2;
}

// ---------------------------------------------------------------------------
// init kernel: zero the output AND (block 0) build the C3 tensors
// ---------------------------------------------------------------------------
__global__ void init_kernel(float* __restrict__ out, int out_size) {
    for (long i = (long)blockIdx.x * blockDim.x + threadIdx.x; i < out_size;
         i += (long)gridDim.x * blockDim.x)
        out[i] = 0.0f;

    if (blockIdx.x != 0) return;

    __shared__ double s_re[1225];
    __shared__ double s_im[1225];
    int tid = threadIdx.x;

    for (int idx = tid; idx < 1225; idx += blockDim.x) {
        int t = 0;
        while (!(idx < CMB_OFF[t + 1])) ++t;
        int lo = CMB_LO[t], li = CMB_LI[t], lf = CMB_LF[t];
        int d2 = 2 * li + 1, d3 = 2 * lf + 1;
        int rel = idx - CMB_OFF[t];
        int a = rel / (d2 * d3), b = (rel / d3) % d2, c = rel % d3;

        int c1[2], c2[2], c3c[2];
        double r1[2], i1[2], r2[2], i2[2], r3[2], i3[2];
        int n1 = cob_row(lo, a, c1, r1, i1);
        int n2 = cob_row(li, b, c2, r2, i2);
        int n3 = cob_row(lf, c, c3c, r3, i3);

        double tr = 0.0, ti = 0.0;
        for (int x = 0; x < n1; ++x)
            for (int y = 0; y < n2; ++y)
                for (int z = 0; z < n3; ++z) {
                    int m1 = c1[x] - lo, m2 = c2[y] - li, m3 = c3c[z] - lf;
                    if (m1 + m2 + m3 != 0) continue;
                    double w = w3j_d(lo, li, lf, m1, m2, m3);
                    if (w == 0.0) continue;
                    double ar = r1[x] * r2[y] - i1[x] * i2[y];
                    double ai = r1[x] * i2[y] + i1[x] * r2[y];
                    double br = ar * r3[z] - ai * i3[z];
                    double bi = ar * i3[z] + ai * r3[z];
                    tr += br * w; ti += bi * w;
                }
        s_re[idx] = tr; s_im[idx] = ti;
    }
    __syncthreads();

    if (tid < 19) {
        int off = CMB_OFF[tid], end = CMB_OFF[tid + 1];
        double nr = 0.0, ni = 0.0;
        for (int k = off; k < end; ++k) { nr += s_re[k] * s_re[k]; ni += s_im[k] * s_im[k]; }
        bool useRe = (nr >= ni);
        double nn = sqrt(useRe ? nr : ni);
        double inv = (nn > 0.0) ? 1.0 / nn : 0.0;
        for (int k = off; k < end; ++k)
            g_C3[k] = (float)((useRe ? s_re[k] : s_im[k]) * inv);
    }
}

// ---------------------------------------------------------------------------
__device__ __forceinline__ float swish_act(float a) {
    return SWISH_SCALE * a / (1.0f + __expf(-a));
}

// 100->100 MLP layer, transposed activations, 4-edge x 2-col register tile
__device__ __forceinline__ void mlp_layer(const float* __restrict__ W,
                                          const float* __restrict__ xin,
                                          float* __restrict__ xout,
                                          float scale, int tid) {
    for (int tt = tid; tt < 200; tt += NT) {
        int e4 = tt & 3;
        int c  = (tt >> 2) << 1;
        const float* xp = xin + e4 * 4;
        const float* Wp = W + c;
        float a00 = 0, a10 = 0, a20 = 0, a30 = 0;
        float a01 = 0, a11 = 0, a21 = 0, a31 = 0;
        #pragma unroll 4
        for (int h = 0; h < 100; ++h) {
            float4 xv = *(const float4*)(xp + h * 16);
            float2 w  = *(const float2*)(Wp + h * 100);
            a00 += xv.x * w.x; a10 += xv.y * w.x; a20 += xv.z * w.x; a30 += xv.w * w.x;
            a01 += xv.x * w.y; a11 += xv.y * w.y; a21 += xv.z * w.y; a31 += xv.w * w.y;
        }
        float4 o0 = make_float4(swish_act(a00 * scale), swish_act(a10 * scale),
                                swish_act(a20 * scale), swish_act(a30 * scale));
        float4 o1 = make_float4(swish_act(a01 * scale), swish_act(a11 * scale),
                                swish_act(a21 * scale), swish_act(a31 * scale));
        *(float4*)(xout + (c + 0) * 16 + e4 * 4) = o0;
        *(float4*)(xout + (c + 1) * 16 + e4 * 4) = o1;
    }
}

// W3 GEMM over a column range: R[le][c] = 0.1 * sum_h x3[le][h] * W3[h][base+c]
// 4-edge x 4-col register tile; activations transposed in smem.
__device__ __forceinline__ void gemm_half(const float* __restrict__ W3,
                                          const float* __restrict__ xB,
                                          float* __restrict__ s_R,
                                          int base, int ncols, int tid) {
    int ntask = ncols;             // (ncols/4 col-groups) * 4 edge-groups
    for (int tt = tid; tt < ntask; tt += NT) {
        int e4 = tt & 3;
        int c  = (tt >> 2) << 2;
        const float* Wp = W3 + base + c;
        const float* xp = xB + e4 * 4;
        float a00=0,a01=0,a02=0,a03=0;
        float a10=0,a11=0,a12=0,a13=0;
        float a20=0,a21=0,a22=0,a23=0;
        float a30=0,a31=0,a32=0,a33=0;
        #pragma unroll 4
        for (int h = 0; h < 100; ++h) {
            float4 xv = *(const float4*)(xp + h * 16);
            float4 w  = *(const float4*)(Wp + (long)h * RTOT);
            a00 += xv.x * w.x; a01 += xv.x * w.y; a02 += xv.x * w.z; a03 += xv.x * w.w;
            a10 += xv.y * w.x; a11 += xv.y * w.y; a12 += xv.y * w.z; a13 += xv.y * w.w;
            a20 += xv.z * w.x; a21 += xv.z * w.y; a22 += xv.z * w.z; a23 += xv.z * w.w;
            a30 += xv.w * w.x; a31 += xv.w * w.y; a32 += xv.w * w.z; a33 += xv.w * w.w;
        }
        int le0 = e4 * 4;
        *(float4*)(s_R + (le0 + 0) * RHALF + c) = make_float4(a00*0.1f, a01*0.1f, a02*0.1f, a03*0.1f);
        *(float4*)(s_R + (le0 + 1) * RHALF + c) = make_float4(a10*0.1f, a11*0.1f, a12*0.1f, a13*0.1f);
        *(float4*)(s_R + (le0 + 2) * RHALF + c) = make_float4(a20*0.1f, a21*0.1f, a22*0.1f, a23*0.1f);
        *(float4*)(s_R + (le0 + 3) * RHALF + c) = make_float4(a30*0.1f, a31*0.1f, a32*0.1f, a33*0.1f);
    }
}

// contraction phase for pairs [p0, p1): acc[u][o] += NRM * sum_{v,fi} R*T
__device__ __forceinline__ void contract_pairs(const float* __restrict__ s_R,
                                               const float* __restrict__ s_T,
                                               float* __restrict__ s_acc,
                                               int p0, int p1, int chbase, int tid) {
    const float NRM[3] = {0.72360125455826753f,   // sqrt(4pi/24)
                          0.82046491430668453f,   // sqrt(4pi*3/56)
                          0.93416143519896869f};  // sqrt(4pi*5/72)
    for (int p = p0; p < p1; ++p) {
        const int no  = 2 * P_LO[p] + 1;
        const int nlf = P_NLF[p];
        const int kl  = 8 * nlf;
        const int osz = 8 * no;
        const int aoff = P_FOFF[p / 3];
        const int roff = P_ROFF[p] - chbase;
        const int toff = T_OFF[p];
        const float nrm = NRM[p / 3];
        for (int t = tid; t < BE * osz; t += NT) {
            int le = t / osz, y = t % osz;
            int u = y / no, o = y % no;
            const float* Rr = s_R + le * RHALF + roff + u * kl;
            const float* Tr = s_T + le * TTOT + toff + o * kl;
            float a = 0.0f;
            #pragma unroll 8
            for (int k = 0; k < kl; ++k) a += Rr[k] * Tr[k];
            s_acc[le * FEATD + aoff + y] += nrm * a;
        }
    }
}

// ---------------------------------------------------------------------------
extern "C" __global__ void __launch_bounds__(NT)
edge_kernel(const float* __restrict__ feat, const int* __restrict__ eidx,
            const float* __restrict__ radii, const float* __restrict__ rsh,
            const float* __restrict__ W0, const float* __restrict__ W1,
            const float* __restrict__ W2, const float* __restrict__ W3,
            float* __restrict__ out, int E)
{
    extern __shared__ float sm[];
    float* s_xA  = sm;                       // [100][16] transposed activations
    float* s_xB  = s_xA + 1600;              // [100][16]
    float* s_R   = s_xB + 1600;              // [16][RHALF]
    float* s_T   = s_R  + BE * RHALF;        // [16][552]
    float* s_F   = s_T  + BE * TTOT;         // [16][72]
    float* s_acc = s_F  + BE * FEATD;        // [16][72]
    float* s_rsh = s_acc + BE * FEATD;       // [16][25]
    int*   s_tgt = (int*)(s_rsh + BE * RSHD);

    const int tid = threadIdx.x;
    const int e0  = blockIdx.x * BE;

    // ---- load per-edge data ----
    if (tid < BE) {
        int e = e0 + tid;
        s_tgt[tid] = (e < E) ? eidx[E + e] : -1;
    }
    for (int t = tid; t < BE * FEATD; t += NT) {
        int le = t / FEATD, k = t % FEATD;
        int e = e0 + le;
        float v = 0.0f;
        if (e < E) v = feat[(long)eidx[e] * FEATD + k];
        s_F[le * FEATD + k] = v;
        s_acc[le * FEATD + k] = 0.0f;
    }
    for (int t = tid; t < BE * RSHD; t += NT) {
        int le = t / RSHD, k = t % RSHD;
        int e = e0 + le;
        s_rsh[le * RSHD + k] = (e < E) ? rsh[e * RSHD + k] : 0.0f;
    }
    // gaussian radial basis, written transposed: s_xA[k][le]
    for (int t = tid; t < BE * 10; t += NT) {
        int k = t / BE, le = t % BE;
        int e = e0 + le;
        float r = (e < E) ? radii[e] : 0.0f;
        const float sigma = 2.5f / 9.0f;
        float c = 0.7f + (float)k * sigma;
        float d = (r - c) / sigma;
        s_xA[k * 16 + le] = __expf(-d * d);
    }
    __syncthreads();

    // ---- layer 0: [10] -> [100], scale 1/sqrt(10), swish. A -> B ----
    for (int tt = tid; tt < 100; tt += NT) {
        int e4 = tt & 3;
        int c  = (tt >> 2) << 2;
        const float* xp = s_xA + e4 * 4;
        const float* Wp = W0 + c;
        float a[4][4] = {};
        #pragma unroll
        for (int h = 0; h < 10; ++h) {
            float4 xv = *(const float4*)(xp + h * 16);
            float4 w  = *(const float4*)(Wp + h * 100);
            a[0][0] += xv.x*w.x; a[0][1] += xv.x*w.y; a[0][2] += xv.x*w.z; a[0][3] += xv.x*w.w;
            a[1][0] += xv.y*w.x; a[1][1] += xv.y*w.y; a[1][2] += xv.y*w.z; a[1][3] += xv.y*w.w;
            a[2][0] += xv.z*w.x; a[2][1] += xv.z*w.y; a[2][2] += xv.z*w.z; a[2][3] += xv.z*w.w;
            a[3][0] += xv.w*w.x; a[3][1] += xv.w*w.y; a[3][2] += xv.w*w.z; a[3][3] += xv.w*w.w;
        }
        const float sc = 0.31622776601683794f;
        #pragma unroll
        for (int cc = 0; cc < 4; ++cc) {
            float4 o = make_float4(swish_act(a[0][cc]*sc), swish_act(a[1][cc]*sc),
                                   swish_act(a[2][cc]*sc), swish_act(a[3][cc]*sc));
            *(float4*)(s_xB + (c + cc) * 16 + e4 * 4) = o;
        }
    }
    __syncthreads();

    // ---- layer 1: B -> A ----
    mlp_layer(W1, s_xB, s_xA, 0.1f, tid);
    __syncthreads();

    // ---- layer 2: A -> B (x3 lives in s_xB) ----
    mlp_layer(W2, s_xA, s_xB, 0.1f, tid);
    __syncthreads();

    // ---- W3 GEMM half 1 (cols 0..639) + T tensors (independent work) ----
    gemm_half(W3, s_xB, s_R, 0, RHALF, tid);

    // T[p][o][v][fi] = sum_mi (sum_mf C3[o,mi,mf]*rsh[lf^2+mf]) * F[v,mi]
    for (int p = 0; p < 9; ++p) {
        const int nlf = P_NLF[p];
        const int no = 2 * P_LO[p] + 1, ni = 2 * P_LI[p] + 1;
        const int tsz = no * 8 * nlf;
        const int j = p % 3;
        for (int t = tid; t < BE * tsz; t += NT) {
            int le = t / tsz, x = t % tsz;
            int o = x / (8 * nlf);
            int rem = x % (8 * nlf);
            int v = rem / nlf, fi = rem % nlf;
            int lf = P_LFMIN[p] + fi;
            int nf = 2 * lf + 1;
            const float* C  = g_C3 + P_C3OFF[p][fi] + o * ni * nf;
            const float* rr = s_rsh + le * RSHD + lf * lf;
            const float* Fv = s_F + le * FEATD + P_FOFF[j] + v * ni;
            float a = 0.0f;
            for (int mi = 0; mi < ni; ++mi) {
                float kv = 0.0f;
                for (int mf = 0; mf < nf; ++mf) kv += C[mi * nf + mf] * rr[mf];
                a += kv * Fv[mi];
            }
            s_T[le * TTOT + T_OFF[p] + x] = a;
        }
    }
    __syncthreads();

    // ---- contraction for pairs 0..5 (cols 0..639) ----
    contract_pairs(s_R, s_T, s_acc, 0, 6, 0, tid);
    __syncthreads();

    // ---- W3 GEMM half 2 (cols 640..1215) ----
    gemm_half(W3, s_xB, s_R, RHALF, RTOT - RHALF, tid);
    __syncthreads();

    // ---- contraction for pairs 6..8 ----
    contract_pairs(s_R, s_T, s_acc, 6, 9, RHALF, tid);
    __syncthreads();

    // ---- scatter-add to target nodes ----
    for (int t = tid; t < BE * FEATD; t += NT) {
        int le = t / FEATD, k = t % FEATD;
        int tg = s_tgt[le];
        if (tg >= 0) atomicAdd(out + (long)tg * FEATD + k, s_acc[le * FEATD + k]);
    }
}

// ---------------------------------------------------------------------------
extern "C" void kernel_launch(void* const* d_in, const int* in_sizes, int n_in,
                              void* d_out, int out_size)
{
    const float* feat  = (const float*)d_in[0];
    const int*   eidx  = (const int*)  d_in[1];
    const float* radii = (const float*)d_in[2];
    const float* rshp  = (const float*)d_in[3];
    const float* W0    = (const float*)d_in[4];
    const float* W1    = (const float*)d_in[5];
    const float* W2    = (const float*)d_in[6];
    const float* W3    = (const float*)d_in[7];
    float* out = (float*)d_out;

    int E = in_sizes[2];   // radii element count = number of edges

    init_kernel<<<256, 256>>>(out, out_size);

    size_t smem = (size_t)(1600 + 1600 + BE * RHALF + BE * TTOT + 2 * BE * FEATD + BE * RSHD) * sizeof(float)
                + (size_t)BE * sizeof(int);
    cudaFuncSetAttribute(edge_kernel, cudaFuncAttributeMaxDynamicSharedMemorySize, (int)smem);

    int nb = (E + BE - 1) / BE;
    edge_kernel<<<nb, NT, smem>>>(feat, eidx, radii, rshp, W0, W1, W2, W3, out, E);
}

// round 6
// speedup vs baseline: 1.7305x; 1.6995x over previous
#include <cuda_runtime.h>
#include <math.h>

#define FEATD   72
#define RTOT    1216
#define RSHD    25
#define SWISH_SCALE 1.679177f

#define MAXE    100352            // max padded edge count (multiple of 128)
#define BE      16                // edges per block in msg kernel
#define NT      256
#define TTOT    552
#define KT      20                // GEMM k-tile (100 = 5 * 20)

// ---------------------------------------------------------------------------
// scratch (static device globals; allocated at module load, legal)
// ---------------------------------------------------------------------------
__device__ float g_C3[1225];
__device__ float g_xT[100 * MAXE];                 // [h][e] transposed x3
__device__ float g_R[(size_t)MAXE * RTOT];         // [e][1216] radial weights

__constant__ int CMB_LO[19] = {0,0,0,1,1,1,1,1,1,1,2,2,2,2,2,2,2,2,2};
__constant__ int CMB_LI[19] = {0,1,2,0,1,1,1,2,2,2,0,1,1,1,2,2,2,2,2};
__constant__ int CMB_LF[19] = {0,1,2,1,0,1,2,1,2,3,2,1,2,3,0,1,2,3,4};
__constant__ int CMB_OFF[20] = {0,1,10,35,44,53,80,125,170,245,350,375,420,495,600,625,700,825,1000,1225};

// pair p = i*3 + j (i: output irrep, j: input irrep), l = {0,1,2}, mul = 8
__constant__ int P_LO[9]   = {0,0,0,1,1,1,2,2,2};
__constant__ int P_LI[9]   = {0,1,2,0,1,2,0,1,2};
__constant__ int P_NLF[9]  = {1,1,1,1,3,3,1,3,5};
__constant__ int P_ROFF[9] = {0,64,128,192,256,448,640,704,896};
__constant__ int P_LFMIN[9]= {0,1,2,1,0,1,2,1,0};
__constant__ int P_FOFF[3] = {0,8,32};
__constant__ int T_OFF[9]  = {0,8,16,24,48,120,192,232,352};
__constant__ int P_C3OFF[9][5] = {
    {0,0,0,0,0},{1,0,0,0,0},{10,0,0,0,0},{35,0,0,0,0},
    {44,53,80,0,0},{125,170,245,0,0},{350,0,0,0,0},
    {375,420,495,0,0},{600,625,700,825,1000}};

// ---------------------------------------------------------------------------
// Wigner 3j (complex basis, Racah) + real change-of-basis, in double
// ---------------------------------------------------------------------------
__device__ __forceinline__ double d_fact(int n) {
    double f = 1.0;
    for (int i = 2; i <= n; ++i) f *= (double)i;
    return f;
}

__device__ double w3j_d(int j1, int j2, int j3, int m1, int m2, int m3) {
    if (m1 + m2 + m3 != 0) return 0.0;
    if (j3 < abs(j1 - j2) || j3 > j1 + j2) return 0.0;
    int t1 = j2 - m1 - j3, t2 = j1 + m2 - j3;
    int kmin = max(0, max(t1, t2));
    int kmax = min(j1 + j2 - j3, min(j1 - m1, j2 + m2));
    double s = 0.0;
    for (int k = kmin; k <= kmax; ++k) {
        double term = 1.0 / (d_fact(k) * d_fact(k - t1) * d_fact(k - t2) *
                             d_fact(j1 + j2 - j3 - k) * d_fact(j1 - m1 - k) * d_fact(j2 + m2 - k));
        s += ((k & 1) ? -term : term);
    }
    double pref = sqrt(
        d_fact(j1 + j2 - j3) * d_fact(j1 - j2 + j3) * d_fact(-j1 + j2 + j3) / d_fact(j1 + j2 + j3 + 1)
        * d_fact(j1 + m1) * d_fact(j1 - m1) * d_fact(j2 + m2) * d_fact(j2 - m2)
        * d_fact(j3 + m3) * d_fact(j3 - m3));
    if ((j1 - j2 - m3) & 1) pref = -pref;
    return pref * s;
}

__device__ __forceinline__ int cob_row(int l, int a, int* cols, double* re, double* im) {
    const double s = 0.70710678118654752440;
    if (a == l) { cols[0] = l; re[0] = 1.0; im[0] = 0.0; return 1; }
    if (a > l) {
        int m = a - l; double sg = (m & 1) ? -1.0 : 1.0;
        cols[0] = l + m; re[0] = sg * s; im[0] = 0.0;
        cols[1] = l - m; re[1] = s;      im[1] = 0.0;
        return 2;
    }
    int m = l - a; double sg = (m & 1) ? -1.0 : 1.0;
    cols[0] = l - m; re[0] = 0.0; im[0] = s;
    cols[1] = l + m; re[1] = 0.0; im[1] = -sg * s;
    return 2;
}

// ---------------------------------------------------------------------------
// init kernel: zero the output AND (block 0) build the C3 tensors
// ---------------------------------------------------------------------------
__global__ void init_kernel(float* __restrict__ out, int out_size) {
    for (long i = (long)blockIdx.x * blockDim.x + threadIdx.x; i < out_size;
         i += (long)gridDim.x * blockDim.x)
        out[i] = 0.0f;

    if (blockIdx.x != 0) return;

    __shared__ double s_re[1225];
    __shared__ double s_im[1225];
    int tid = threadIdx.x;

    for (int idx = tid; idx < 1225; idx += blockDim.x) {
        int t = 0;
        while (!(idx < CMB_OFF[t + 1])) ++t;
        int lo = CMB_LO[t], li = CMB_LI[t], lf = CMB_LF[t];
        int d2 = 2 * li + 1, d3 = 2 * lf + 1;
        int rel = idx - CMB_OFF[t];
        int a = rel / (d2 * d3), b = (rel / d3) % d2, c = rel % d3;

        int c1[2], c2[2], c3c[2];
        double r1[2], i1[2], r2[2], i2[2], r3[2], i3[2];
        int n1 = cob_row(lo, a, c1, r1, i1);
        int n2 = cob_row(li, b, c2, r2, i2);
        int n3 = cob_row(lf, c, c3c, r3, i3);

        double tr = 0.0, ti = 0.0;
        for (int x = 0; x < n1; ++x)
            for (int y = 0; y < n2; ++y)
                for (int z = 0; z < n3; ++z) {
                    int m1 = c1[x] - lo, m2 = c2[y] - li, m3 = c3c[z] - lf;
                    if (m1 + m2 + m3 != 0) continue;
                    double w = w3j_d(lo, li, lf, m1, m2, m3);
                    if (w == 0.0) continue;
                    double ar = r1[x] * r2[y] - i1[x] * i2[y];
                    double ai = r1[x] * i2[y] + i1[x] * r2[y];
                    double br = ar * r3[z] - ai * i3[z];
                    double bi = ar * i3[z] + ai * r3[z];
                    tr += br * w; ti += bi * w;
                }
        s_re[idx] = tr; s_im[idx] = ti;
    }
    __syncthreads();

    if (tid < 19) {
        int off = CMB_OFF[tid], end = CMB_OFF[tid + 1];
        double nr = 0.0, ni = 0.0;
        for (int k = off; k < end; ++k) { nr += s_re[k] * s_re[k]; ni += s_im[k] * s_im[k]; }
        bool useRe = (nr >= ni);
        double nn = sqrt(useRe ? nr : ni);
        double inv = (nn > 0.0) ? 1.0 / nn : 0.0;
        for (int k = off; k < end; ++k)
            g_C3[k] = (float)((useRe ? s_re[k] : s_im[k]) * inv);
    }
}

// ---------------------------------------------------------------------------
__device__ __forceinline__ float swish_act(float a) {
    return SWISH_SCALE * a / (1.0f + __expf(-a));
}

// K->100 layer on a 64-edge tile, transposed activations [k][64]
__device__ __forceinline__ void mlpA_layer(const float* __restrict__ W,
                                           const float* __restrict__ xin,
                                           float* __restrict__ xout,
                                           int K, float scale, int tid) {
    for (int tt = tid; tt < 800; tt += 256) {
        int e4 = tt & 15;
        int c  = (tt >> 4) << 1;
        const float* xp = xin + e4 * 4;
        const float* Wp = W + c;
        float a00 = 0, a10 = 0, a20 = 0, a30 = 0;
        float a01 = 0, a11 = 0, a21 = 0, a31 = 0;
        #pragma unroll 4
        for (int h = 0; h < K; ++h) {
            float4 xv = *(const float4*)(xp + h * 64);
            float2 w  = *(const float2*)(Wp + h * 100);
            a00 += xv.x * w.x; a10 += xv.y * w.x; a20 += xv.z * w.x; a30 += xv.w * w.x;
            a01 += xv.x * w.y; a11 += xv.y * w.y; a21 += xv.z * w.y; a31 += xv.w * w.y;
        }
        *(float4*)(xout + (c + 0) * 64 + e4 * 4) =
            make_float4(swish_act(a00 * scale), swish_act(a10 * scale),
                        swish_act(a20 * scale), swish_act(a30 * scale));
        *(float4*)(xout + (c + 1) * 64 + e4 * 4) =
            make_float4(swish_act(a01 * scale), swish_act(a11 * scale),
                        swish_act(a21 * scale), swish_act(a31 * scale));
    }
}

// ---------------------------------------------------------------------------
// kernel A: radial MLP -> g_xT[h][e]  (transposed)
// ---------------------------------------------------------------------------
__global__ void __launch_bounds__(256)
mlp_kernel(const float* __restrict__ radii,
           const float* __restrict__ W0, const float* __restrict__ W1,
           const float* __restrict__ W2, int E, int EPAD)
{
    extern __shared__ float sm[];
    float* s_h1 = sm;            // [100][64]
    float* s_h2 = s_h1 + 6400;   // [100][64]
    float* s_b  = s_h2 + 6400;   // [10][64]

    const int tid = threadIdx.x;
    const int e0  = blockIdx.x * 64;

    // gaussian radial basis, transposed
    for (int t = tid; t < 640; t += 256) {
        int k = t >> 6, le = t & 63;
        int e = e0 + le;
        float r = (e < E) ? radii[e] : 0.0f;
        const float sigma = 2.5f / 9.0f;
        float c = 0.7f + (float)k * sigma;
        float d = (r - c) / sigma;
        s_b[k * 64 + le] = __expf(-d * d);
    }
    __syncthreads();

    mlpA_layer(W0, s_b, s_h1, 10, 0.31622776601683794f, tid);
    __syncthreads();
    mlpA_layer(W1, s_h1, s_h2, 100, 0.1f, tid);
    __syncthreads();

    // layer 2 -> gmem (transposed, stride EPAD)
    for (int tt = tid; tt < 800; tt += 256) {
        int e4 = tt & 15;
        int c  = (tt >> 4) << 1;
        const float* xp = s_h2 + e4 * 4;
        const float* Wp = W2 + c;
        float a00 = 0, a10 = 0, a20 = 0, a30 = 0;
        float a01 = 0, a11 = 0, a21 = 0, a31 = 0;
        #pragma unroll 4
        for (int h = 0; h < 100; ++h) {
            float4 xv = *(const float4*)(xp + h * 64);
            float2 w  = *(const float2*)(Wp + h * 100);
            a00 += xv.x * w.x; a10 += xv.y * w.x; a20 += xv.z * w.x; a30 += xv.w * w.x;
            a01 += xv.x * w.y; a11 += xv.y * w.y; a21 += xv.z * w.y; a31 += xv.w * w.y;
        }
        *(float4*)(g_xT + (size_t)(c + 0) * EPAD + e0 + e4 * 4) =
            make_float4(swish_act(a00 * 0.1f), swish_act(a10 * 0.1f),
                        swish_act(a20 * 0.1f), swish_act(a30 * 0.1f));
        *(float4*)(g_xT + (size_t)(c + 1) * EPAD + e0 + e4 * 4) =
            make_float4(swish_act(a01 * 0.1f), swish_act(a11 * 0.1f),
                        swish_act(a21 * 0.1f), swish_act(a31 * 0.1f));
    }
}

// ---------------------------------------------------------------------------
// kernel B: R = xT^T @ W3 * 0.1   (M=EPAD, N=1216, K=100)
// block tile 128x64, thread tile 8x4, cp.async double-buffered k-tiles of 20
// ---------------------------------------------------------------------------
__device__ __forceinline__ void cp_async16(void* sdst, const void* gsrc) {
    unsigned sa = (unsigned)__cvta_generic_to_shared(sdst);
    asm volatile("cp.async.cg.shared.global [%0], [%1], 16;\n" :: "r"(sa), "l"(gsrc));
}

__global__ void __launch_bounds__(256)
gemm_kernel(const float* __restrict__ W3, int EPAD)
{
    __shared__ float As[2][KT][128];
    __shared__ float Bs[2][KT][64];

    const int tid = threadIdx.x;
    const int m0 = blockIdx.y * 128;
    const int n0 = blockIdx.x * 64;
    const int tn = tid & 15;
    const int tm = tid >> 4;

    // tile loader
    auto issue = [&](int t, int buf) {
        int k0 = t * KT;
        #pragma unroll
        for (int i = tid; i < 640; i += 256) {          // A: 20 x 128 floats
            int r = i >> 5, c = i & 31;
            cp_async16(&As[buf][r][c * 4], g_xT + (size_t)(k0 + r) * EPAD + m0 + c * 4);
        }
        #pragma unroll
        for (int i = tid; i < 320; i += 256) {          // B: 20 x 64 floats
            int r = i >> 4, c = i & 15;
            cp_async16(&Bs[buf][r][c * 4], W3 + (size_t)(k0 + r) * RTOT + n0 + c * 4);
        }
        asm volatile("cp.async.commit_group;\n");
    };

    float acc[8][4] = {};

    issue(0, 0);
    for (int t = 0; t < 5; ++t) {
        if (t < 4) {
            issue(t + 1, (t + 1) & 1);
            asm volatile("cp.async.wait_group 1;\n");
        } else {
            asm volatile("cp.async.wait_group 0;\n");
        }
        __syncthreads();

        const float (*Asb)[128] = As[t & 1];
        const float (*Bsb)[64]  = Bs[t & 1];
        #pragma unroll
        for (int kk = 0; kk < KT; ++kk) {
            float4 a0 = *(const float4*)&Asb[kk][tm * 8];
            float4 a1 = *(const float4*)&Asb[kk][tm * 8 + 4];
            float4 b  = *(const float4*)&Bsb[kk][tn * 4];
            float av[8] = {a0.x, a0.y, a0.z, a0.w, a1.x, a1.y, a1.z, a1.w};
            #pragma unroll
            for (int i = 0; i < 8; ++i) {
                acc[i][0] += av[i] * b.x;
                acc[i][1] += av[i] * b.y;
                acc[i][2] += av[i] * b.z;
                acc[i][3] += av[i] * b.w;
            }
        }
        __syncthreads();
    }

    // epilogue: fold the 1/sqrt(100) scale, write coalesced float4
    #pragma unroll
    for (int i = 0; i < 8; ++i) {
        size_t row = (size_t)(m0 + tm * 8 + i);
        *(float4*)(g_R + row * RTOT + n0 + tn * 4) =
            make_float4(acc[i][0] * 0.1f, acc[i][1] * 0.1f,
                        acc[i][2] * 0.1f, acc[i][3] * 0.1f);
    }
}

// ---------------------------------------------------------------------------
// kernel C: tensor-product message + scatter-add, R streamed from gmem
// ---------------------------------------------------------------------------
__global__ void __launch_bounds__(NT)
msg_kernel(const float* __restrict__ feat, const int* __restrict__ eidx,
           const float* __restrict__ rsh, float* __restrict__ out, int E)
{
    __shared__ float s_T[BE * TTOT];     // [16][552]
    __shared__ float s_F[BE * FEATD];
    __shared__ float s_acc[BE * FEATD];
    __shared__ float s_rsh[BE * RSHD];
    __shared__ int   s_tgt[BE];

    const int tid = threadIdx.x;
    const int e0  = blockIdx.x * BE;

    if (tid < BE) {
        int e = e0 + tid;
        s_tgt[tid] = (e < E) ? eidx[E + e] : -1;
    }
    for (int t = tid; t < BE * FEATD; t += NT) {
        int le = t / FEATD, k = t % FEATD;
        int e = e0 + le;
        float v = 0.0f;
        if (e < E) v = feat[(long)eidx[e] * FEATD + k];
        s_F[le * FEATD + k] = v;
        s_acc[le * FEATD + k] = 0.0f;
    }
    for (int t = tid; t < BE * RSHD; t += NT) {
        int le = t / RSHD, k = t % RSHD;
        int e = e0 + le;
        s_rsh[le * RSHD + k] = (e < E) ? rsh[e * RSHD + k] : 0.0f;
    }
    __syncthreads();

    // T[p][o][v][fi] = sum_mi (sum_mf C3[o,mi,mf]*rsh[lf^2+mf]) * F[v,mi]
    for (int p = 0; p < 9; ++p) {
        const int nlf = P_NLF[p];
        const int no = 2 * P_LO[p] + 1, ni = 2 * P_LI[p] + 1;
        const int tsz = no * 8 * nlf;
        const int j = p % 3;
        for (int t = tid; t < BE * tsz; t += NT) {
            int le = t / tsz, x = t % tsz;
            int o = x / (8 * nlf);
            int rem = x % (8 * nlf);
            int v = rem / nlf, fi = rem % nlf;
            int lf = P_LFMIN[p] + fi;
            int nf = 2 * lf + 1;
            const float* C  = g_C3 + P_C3OFF[p][fi] + o * ni * nf;
            const float* rr = s_rsh + le * RSHD + lf * lf;
            const float* Fv = s_F + le * FEATD + P_FOFF[j] + v * ni;
            float a = 0.0f;
            for (int mi = 0; mi < ni; ++mi) {
                float kv = 0.0f;
                for (int mf = 0; mf < nf; ++mf) kv += C[mi * nf + mf] * rr[mf];
                a += kv * Fv[mi];
            }
            s_T[le * TTOT + T_OFF[p] + x] = a;
        }
    }
    __syncthreads();

    // contraction: acc[u][o] += NRM * sum_{v,fi} R[e,u,v,fi] * T[o,v,fi]
    const float NRM[3] = {0.72360125455826753f,   // sqrt(4pi/24)
                          0.82046491430668453f,   // sqrt(4pi*3/56)
                          0.93416143519896869f};  // sqrt(4pi*5/72)
    for (int p = 0; p < 9; ++p) {
        const int no  = 2 * P_LO[p] + 1;
        const int nlf = P_NLF[p];
        const int kl  = 8 * nlf;
        const int kq  = kl >> 2;
        const int osz = 8 * no;
        const int aoff = P_FOFF[p / 3];
        const int toff = T_OFF[p];
        const float nrm = NRM[p / 3];
        for (int t = tid; t < BE * osz; t += NT) {
            int le = t / osz, y = t % osz;
            int u = y / no, o = y % no;
            size_t e = (size_t)(e0 + le);
            const float4* Rr = (const float4*)(g_R + e * RTOT + P_ROFF[p] + u * kl);
            const float4* Tr = (const float4*)(s_T + le * TTOT + toff + o * kl);
            float a = 0.0f;
            for (int k = 0; k < kq; ++k) {
                float4 rv = __ldg(Rr + k);
                float4 tv = Tr[k];
                a += rv.x * tv.x + rv.y * tv.y + rv.z * tv.z + rv.w * tv.w;
            }
            s_acc[le * FEATD + aoff + y] += nrm * a;
        }
    }
    __syncthreads();

    // scatter-add
    for (int t = tid; t < BE * FEATD; t += NT) {
        int le = t / FEATD, k = t % FEATD;
        int tg = s_tgt[le];
        if (tg >= 0) atomicAdd(out + (long)tg * FEATD + k, s_acc[le * FEATD + k]);
    }
}

// ---------------------------------------------------------------------------
extern "C" void kernel_launch(void* const* d_in, const int* in_sizes, int n_in,
                              void* d_out, int out_size)
{
    const float* feat  = (const float*)d_in[0];
    const int*   eidx  = (const int*)  d_in[1];
    const float* radii = (const float*)d_in[2];
    const float* rshp  = (const float*)d_in[3];
    const float* W0    = (const float*)d_in[4];
    const float* W1    = (const float*)d_in[5];
    const float* W2    = (const float*)d_in[6];
    const float* W3    = (const float*)d_in[7];
    float* out = (float*)d_out;

    int E = in_sizes[2];                       // radii count = edges
    int EPAD = ((E + 127) / 128) * 128;
    if (EPAD > MAXE) EPAD = MAXE;

    init_kernel<<<256, 256>>>(out, out_size);

    // kernel A: radial MLP (64 edges / block, dynamic smem 53.8 KB)
    size_t smemA = (size_t)(2 * 6400 + 640) * sizeof(float);
    cudaFuncSetAttribute(mlp_kernel, cudaFuncAttributeMaxDynamicSharedMemorySize, (int)smemA);
    mlp_kernel<<<EPAD / 64, 256, smemA>>>(radii, W0, W1, W2, E, EPAD);

    // kernel B: big GEMM
    dim3 gB(RTOT / 64, EPAD / 128);
    gemm_kernel<<<gB, 256>>>(W3, EPAD);

    // kernel C: message + scatter
    msg_kernel<<<(E + BE - 1) / BE, NT>>>(feat, eidx, rshp, out, E);
}